// round 2
// baseline (speedup 1.0000x reference)
#include <cuda_runtime.h>
#include <cstdint>

#define M_TOTAL 32768      // B*N = 8*4096
#define D_EMB   768
#define VOCAB   4096
#define HID     128
#define KH      256        // concat hidden (spatial 128 + feature 128)

#define BM 128
#define BN 128
#define BKV 8              // vq k-tile (double buffered)
#define BK 16              // embed gemm k-tile

// Scratch (no cudaMalloc allowed)
__device__ float g_H[M_TOTAL * KH];             // hidden activations [M, 256]
__device__ float g_X[(size_t)M_TOTAL * D_EMB];  // combined embedding [M, 768]
__device__ float g_csq[VOCAB];                  // ||c||^2

typedef unsigned long long u64;

__device__ __forceinline__ u64 pack2(float x, float y) {
    u64 r;
    unsigned xi = __float_as_uint(x), yi = __float_as_uint(y);
    asm("mov.b64 %0, {%1, %2};" : "=l"(r) : "r"(xi), "r"(yi));
    return r;
}
__device__ __forceinline__ void unpack2(u64 v, float& x, float& y) {
    unsigned xi, yi;
    asm("mov.b64 {%0, %1}, %2;" : "=r"(xi), "=r"(yi) : "l"(v));
    x = __uint_as_float(xi); y = __uint_as_float(yi);
}
__device__ __forceinline__ u64 fma2(u64 a, u64 b, u64 c) {
    u64 d;
    asm("fma.rn.f32x2 %0, %1, %2, %3;" : "=l"(d) : "l"(a), "l"(b), "l"(c));
    return d;
}

// ---------------------------------------------------------------------------
// Kernel 1: hidden activations H[m, 0:128] = relu(coords@Ws1+bs1),
//                              H[m, 128:256] = relu(feats@Wf1+bf1)
// ---------------------------------------------------------------------------
__global__ void hidden_kernel(const float* __restrict__ coords,
                              const float* __restrict__ feats,
                              const float* __restrict__ Ws1, const float* __restrict__ bs1,
                              const float* __restrict__ Wf1, const float* __restrict__ bf1) {
    int t = blockIdx.x * blockDim.x + threadIdx.x;   // [0, M*256)
    int m = t >> 8;
    int j = t & 255;
    float acc;
    if (j < HID) {
        float c0 = coords[m * 2 + 0];
        float c1 = coords[m * 2 + 1];
        acc = bs1[j] + c0 * Ws1[j] + c1 * Ws1[HID + j];
    } else {
        int jj = j - HID;
        acc = bf1[jj];
#pragma unroll
        for (int i = 0; i < 10; i++)
            acc += feats[m * 10 + i] * Wf1[i * HID + jj];
    }
    g_H[t] = fmaxf(acc, 0.0f);
}

// ---------------------------------------------------------------------------
// Kernel 2: per-codeword squared norms
// ---------------------------------------------------------------------------
__global__ void csq_kernel(const float* __restrict__ cb) {
    int w = (blockIdx.x * blockDim.x + threadIdx.x) >> 5;
    int lane = threadIdx.x & 31;
    if (w >= VOCAB) return;
    const float* row = cb + (size_t)w * D_EMB;
    float s = 0.f;
    for (int i = lane; i < D_EMB; i += 32) { float v = row[i]; s += v * v; }
#pragma unroll
    for (int o = 16; o; o >>= 1) s += __shfl_down_sync(0xffffffffu, s, o);
    if (lane == 0) g_csq[w] = s;
}

// ---------------------------------------------------------------------------
// Kernel 3: X = H[32768,256] @ W2cat[256,768] + (bs2+bf2)  (unchanged, ~4% of time)
// ---------------------------------------------------------------------------
__global__ __launch_bounds__(256) void embed_gemm_kernel(
    const float* __restrict__ Ws2, const float* __restrict__ bs2,
    const float* __restrict__ Wf2, const float* __restrict__ bf2) {
    __shared__ float As[BK][BM];
    __shared__ float Bs[BK][BN];
    int tid = threadIdx.x;
    int tx = tid & 15, ty = tid >> 4;
    int m0 = blockIdx.x * BM;
    int n0 = blockIdx.y * BN;

    u64 acc[8][4];
#pragma unroll
    for (int i = 0; i < 8; i++)
#pragma unroll
        for (int j = 0; j < 4; j++) acc[i][j] = 0ull;

    for (int kt = 0; kt < KH / BK; kt++) {
#pragma unroll
        for (int e = 0; e < 2; e++) {
            int s = tid * 2 + e;
            int m = s >> 2, kq = s & 3;
            float4 v = *(const float4*)(g_H + (size_t)(m0 + m) * KH + kt * BK + kq * 4);
            As[kq * 4 + 0][m] = v.x; As[kq * 4 + 1][m] = v.y;
            As[kq * 4 + 2][m] = v.z; As[kq * 4 + 3][m] = v.w;
        }
#pragma unroll
        for (int e = 0; e < 2; e++) {
            int s = tid * 2 + e;
            int k = s >> 5;
            int n = (s & 31) * 4;
            int kg = kt * BK + k;
            const float* src = (kg < HID) ? (Ws2 + (size_t)kg * D_EMB)
                                          : (Wf2 + (size_t)(kg - HID) * D_EMB);
            *(float4*)&Bs[k][n] = *(const float4*)(src + n0 + n);
        }
        __syncthreads();
#pragma unroll
        for (int k = 0; k < BK; k++) {
            ulonglong2 p0 = *(const ulonglong2*)&Bs[k][tx * 8];
            ulonglong2 p1 = *(const ulonglong2*)&Bs[k][tx * 8 + 4];
            u64 b[4] = {p0.x, p0.y, p1.x, p1.y};
            float4 a0 = *(const float4*)&As[k][ty * 8];
            float4 a1 = *(const float4*)&As[k][ty * 8 + 4];
            u64 ad[8];
            ad[0] = pack2(a0.x, a0.x); ad[1] = pack2(a0.y, a0.y);
            ad[2] = pack2(a0.z, a0.z); ad[3] = pack2(a0.w, a0.w);
            ad[4] = pack2(a1.x, a1.x); ad[5] = pack2(a1.y, a1.y);
            ad[6] = pack2(a1.z, a1.z); ad[7] = pack2(a1.w, a1.w);
#pragma unroll
            for (int i = 0; i < 8; i++)
#pragma unroll
                for (int j = 0; j < 4; j++)
                    acc[i][j] = fma2(ad[i], b[j], acc[i][j]);
        }
        __syncthreads();
    }
#pragma unroll
    for (int j = 0; j < 4; j++) {
        int c = n0 + tx * 8 + j * 2;
        float bb0 = bs2[c] + bf2[c];
        float bb1 = bs2[c + 1] + bf2[c + 1];
#pragma unroll
        for (int i = 0; i < 8; i++) {
            float lo, hi; unpack2(acc[i][j], lo, hi);
            float2 o = make_float2(lo + bb0, hi + bb1);
            *(float2*)(g_X + (size_t)(m0 + ty * 8 + i) * D_EMB + c) = o;
        }
    }
}

// ---------------------------------------------------------------------------
// Kernel 4: VQ — double-buffered, duplicated-A layout, shuffle argmin.
// dist = ||c||^2 - 2 x.c ; per block: 128 rows x full vocab.
// ---------------------------------------------------------------------------
#define NVT (VOCAB / BN)     // 32
#define NKT (D_EMB / BKV)    // 96

__global__ __launch_bounds__(256, 2) void vq_kernel(const float* __restrict__ cb,
                                                    float* __restrict__ out_tok,
                                                    float* __restrict__ out_q) {
    __shared__ float As2[2][BKV][2 * BM];      // duplicated A pairs: 16 KB
    __shared__ float Bs[2][BKV][BN + 4];       // padded: ~8.25 KB
    __shared__ int   s_tok[BM];

    int tid = threadIdx.x;
    int tx = tid & 15, ty = tid >> 4;
    int m0 = blockIdx.x * BM;

    // fill-role indices: each thread owns one float4 per tile
    int fm = tid >> 1;        // 0..127 (row within tile)
    int fq = tid & 1;         // which half of BKV=8 (4 k's each)
    const float* aptr = g_X + (size_t)(m0 + fm) * D_EMB + fq * 4;

    float bv[8]; int bi[8];
#pragma unroll
    for (int i = 0; i < 8; i++) { bv[i] = 3.4e38f; bi[i] = 0; }

    // prefetch tile (vt=0, kt=0) straight into stage 0
    {
        float4 ra = *(const float4*)(aptr);
        float4 rb = *(const float4*)(cb + (size_t)fm * D_EMB + fq * 4);
        *(float2*)&As2[0][fq * 4 + 0][2 * fm] = make_float2(ra.x, ra.x);
        *(float2*)&As2[0][fq * 4 + 1][2 * fm] = make_float2(ra.y, ra.y);
        *(float2*)&As2[0][fq * 4 + 2][2 * fm] = make_float2(ra.z, ra.z);
        *(float2*)&As2[0][fq * 4 + 3][2 * fm] = make_float2(ra.w, ra.w);
        Bs[0][fq * 4 + 0][fm] = rb.x;
        Bs[0][fq * 4 + 1][fm] = rb.y;
        Bs[0][fq * 4 + 2][fm] = rb.z;
        Bs[0][fq * 4 + 3][fm] = rb.w;
    }
    __syncthreads();

    int st = 0;
    for (int vt = 0; vt < NVT; vt++) {
        u64 acc[8][4];
#pragma unroll
        for (int i = 0; i < 8; i++)
#pragma unroll
            for (int j = 0; j < 4; j++) acc[i][j] = 0ull;

        for (int kt = 0; kt < NKT; kt++) {
            int nkt = kt + 1, nvt = vt;
            if (nkt == NKT) { nkt = 0; nvt = vt + 1; }
            bool hn = (nvt < NVT);
            float4 ra, rb;
            if (hn) {
                ra = *(const float4*)(aptr + nkt * BKV);
                rb = *(const float4*)(cb + (size_t)(nvt * BN + fm) * D_EMB + nkt * BKV + fq * 4);
            }
            // compute current stage
#pragma unroll
            for (int k = 0; k < BKV; k++) {
                const ulonglong2* pa = (const ulonglong2*)&As2[st][k][ty * 16];
                ulonglong2 a01 = pa[0], a23 = pa[1], a45 = pa[2], a67 = pa[3];
                const ulonglong2* pb = (const ulonglong2*)&Bs[st][k][tx * 8];
                ulonglong2 b01 = pb[0], b23 = pb[1];
                u64 a[8] = {a01.x, a01.y, a23.x, a23.y, a45.x, a45.y, a67.x, a67.y};
                u64 b[4] = {b01.x, b01.y, b23.x, b23.y};
#pragma unroll
                for (int i = 0; i < 8; i++)
#pragma unroll
                    for (int j = 0; j < 4; j++)
                        acc[i][j] = fma2(a[i], b[j], acc[i][j]);
            }
            if (hn) {
                int so = st ^ 1;
                *(float2*)&As2[so][fq * 4 + 0][2 * fm] = make_float2(ra.x, ra.x);
                *(float2*)&As2[so][fq * 4 + 1][2 * fm] = make_float2(ra.y, ra.y);
                *(float2*)&As2[so][fq * 4 + 2][2 * fm] = make_float2(ra.z, ra.z);
                *(float2*)&As2[so][fq * 4 + 3][2 * fm] = make_float2(ra.w, ra.w);
                Bs[so][fq * 4 + 0][fm] = rb.x;
                Bs[so][fq * 4 + 1][fm] = rb.y;
                Bs[so][fq * 4 + 2][fm] = rb.z;
                Bs[so][fq * 4 + 3][fm] = rb.w;
            }
            __syncthreads();
            st ^= 1;
        }

        // fold this vocab tile: dist = csq[v] - 2*dot
        int v0 = vt * BN;
#pragma unroll
        for (int j = 0; j < 4; j++) {
            int v = v0 + tx * 8 + j * 2;
            float c0 = g_csq[v], c1 = g_csq[v + 1];
#pragma unroll
            for (int i = 0; i < 8; i++) {
                float lo, hi; unpack2(acc[i][j], lo, hi);
                float d0 = fmaf(-2.0f, lo, c0);
                float d1 = fmaf(-2.0f, hi, c1);
                if (d0 < bv[i]) { bv[i] = d0; bi[i] = v; }
                if (d1 < bv[i]) { bv[i] = d1; bi[i] = v + 1; }
            }
        }
    }

    // cross-tx argmin via shuffles (candidates for row ty*8+i live in the
    // 16 lanes sharing ty within this warp; xor masks <16 stay in-half)
#pragma unroll
    for (int i = 0; i < 8; i++) {
        float v = bv[i]; int ix = bi[i];
#pragma unroll
        for (int mask = 8; mask; mask >>= 1) {
            float ov = __shfl_xor_sync(0xffffffffu, v, mask);
            int   oi = __shfl_xor_sync(0xffffffffu, ix, mask);
            if (ov < v || (ov == v && oi < ix)) { v = ov; ix = oi; }
        }
        if (tx == 0) {
            int r = ty * 8 + i;
            out_tok[m0 + r] = (float)ix;
            s_tok[r] = ix;
        }
    }
    __syncthreads();

    // gather quantized rows from codebook (L2-hot)
    for (int s2 = tid; s2 < BM * (D_EMB / 4); s2 += 256) {
        int r = s2 / (D_EMB / 4);
        int c = (s2 % (D_EMB / 4)) * 4;
        float4 v = *(const float4*)(cb + (size_t)s_tok[r] * D_EMB + c);
        *(float4*)(out_q + (size_t)(m0 + r) * D_EMB + c) = v;
    }
}

// ---------------------------------------------------------------------------
extern "C" void kernel_launch(void* const* d_in, const int* in_sizes, int n_in,
                              void* d_out, int out_size) {
    const float* coords = (const float*)d_in[0];
    const float* feats  = (const float*)d_in[1];
    const float* Ws1 = (const float*)d_in[2];
    const float* bs1 = (const float*)d_in[3];
    const float* Ws2 = (const float*)d_in[4];
    const float* bs2 = (const float*)d_in[5];
    const float* Wf1 = (const float*)d_in[6];
    const float* bf1 = (const float*)d_in[7];
    const float* Wf2 = (const float*)d_in[8];
    const float* bf2 = (const float*)d_in[9];
    const float* cb  = (const float*)d_in[10];

    float* outf    = (float*)d_out;
    float* out_tok = outf;                 // tokens [32768] as float
    float* out_q   = outf + M_TOTAL;       // quantized [32768, 768]

    hidden_kernel<<<M_TOTAL, 256>>>(coords, feats, Ws1, bs1, Wf1, bf1);
    csq_kernel<<<VOCAB / 8, 256>>>(cb);
    dim3 g2(M_TOTAL / BM, D_EMB / BN);
    embed_gemm_kernel<<<g2, 256>>>(Ws2, bs2, Wf2, bf2);
    vq_kernel<<<M_TOTAL / BM, 256>>>(cb, out_tok, out_q);
}

// round 4
// speedup vs baseline: 3.1077x; 3.1077x over previous
#include <cuda_runtime.h>
#include <cuda_fp16.h>
#include <cstdint>

#define M_TOTAL 32768      // B*N
#define D_EMB   768
#define VOCAB   4096
#define HID     128
#define KH      256

// ---------------- scratch globals (no cudaMalloc allowed) -------------------
__device__ float g_H[M_TOTAL * KH];
__device__ __align__(16) __half g_Xh[(size_t)M_TOTAL * D_EMB];
__device__ __align__(16) __half g_Xl[(size_t)M_TOTAL * D_EMB];
__device__ __align__(16) __half g_Ch[(size_t)VOCAB * D_EMB];
__device__ __align__(16) __half g_Cl[(size_t)VOCAB * D_EMB];
__device__ float g_csq[VOCAB];

typedef unsigned long long u64;

// ---------------- f32x2 helpers (embed gemm) --------------------------------
__device__ __forceinline__ u64 pack2(float x, float y) {
    u64 r; unsigned xi = __float_as_uint(x), yi = __float_as_uint(y);
    asm("mov.b64 %0, {%1, %2};" : "=l"(r) : "r"(xi), "r"(yi));
    return r;
}
__device__ __forceinline__ void unpack2(u64 v, float& x, float& y) {
    unsigned xi, yi;
    asm("mov.b64 {%0, %1}, %2;" : "=r"(xi), "=r"(yi) : "l"(v));
    x = __uint_as_float(xi); y = __uint_as_float(yi);
}
__device__ __forceinline__ u64 fma2(u64 a, u64 b, u64 c) {
    u64 d; asm("fma.rn.f32x2 %0, %1, %2, %3;" : "=l"(d) : "l"(a), "l"(b), "l"(c));
    return d;
}

// ---------------- mma.sync helpers ------------------------------------------
__device__ __forceinline__ uint32_t smem_to_u32(const void* p) {
    uint32_t a;
    asm("{ .reg .u64 t; cvta.to.shared.u64 t, %1; cvt.u32.u64 %0, t; }" : "=r"(a) : "l"(p));
    return a;
}
__device__ __forceinline__ void ldsm4(uint32_t* r, uint32_t addr) {
    asm volatile("ldmatrix.sync.aligned.m8n8.x4.shared.b16 {%0,%1,%2,%3}, [%4];"
        : "=r"(r[0]), "=r"(r[1]), "=r"(r[2]), "=r"(r[3]) : "r"(addr));
}
__device__ __forceinline__ void mma16816(float* c, const uint32_t* a, const uint32_t* b) {
    asm volatile("mma.sync.aligned.m16n8k16.row.col.f32.f16.f16.f32 "
        "{%0,%1,%2,%3}, {%4,%5,%6,%7}, {%8,%9}, {%0,%1,%2,%3};"
        : "+f"(c[0]), "+f"(c[1]), "+f"(c[2]), "+f"(c[3])
        : "r"(a[0]), "r"(a[1]), "r"(a[2]), "r"(a[3]), "r"(b[0]), "r"(b[1]));
}
__device__ __forceinline__ void cp_async16(uint32_t dst, const void* src) {
    asm volatile("cp.async.cg.shared.global [%0], [%1], 16;" :: "r"(dst), "l"(src) : "memory");
}
#define CP_COMMIT() asm volatile("cp.async.commit_group;" ::: "memory")
#define CP_WAIT0()  asm volatile("cp.async.wait_group 0;" ::: "memory")

// ---------------------------------------------------------------------------
// Kernel 1: hidden activations
// ---------------------------------------------------------------------------
__global__ void hidden_kernel(const float* __restrict__ coords,
                              const float* __restrict__ feats,
                              const float* __restrict__ Ws1, const float* __restrict__ bs1,
                              const float* __restrict__ Wf1, const float* __restrict__ bf1) {
    int t = blockIdx.x * blockDim.x + threadIdx.x;
    int m = t >> 8;
    int j = t & 255;
    float acc;
    if (j < HID) {
        float c0 = coords[m * 2 + 0];
        float c1 = coords[m * 2 + 1];
        acc = bs1[j] + c0 * Ws1[j] + c1 * Ws1[HID + j];
    } else {
        int jj = j - HID;
        acc = bf1[jj];
#pragma unroll
        for (int i = 0; i < 10; i++)
            acc += feats[m * 10 + i] * Wf1[i * HID + jj];
    }
    g_H[t] = fmaxf(acc, 0.0f);
}

// ---------------------------------------------------------------------------
// Kernel 2: codebook squared norms
// ---------------------------------------------------------------------------
__global__ void csq_kernel(const float* __restrict__ cb) {
    int w = (blockIdx.x * blockDim.x + threadIdx.x) >> 5;
    int lane = threadIdx.x & 31;
    if (w >= VOCAB) return;
    const float* row = cb + (size_t)w * D_EMB;
    float s = 0.f;
    for (int i = lane; i < D_EMB; i += 32) { float v = row[i]; s += v * v; }
#pragma unroll
    for (int o = 16; o; o >>= 1) s += __shfl_down_sync(0xffffffffu, s, o);
    if (lane == 0) g_csq[w] = s;
}

// ---------------------------------------------------------------------------
// Kernel 2b: split codebook into f16 hi/lo
// ---------------------------------------------------------------------------
__global__ void split_cb_kernel(const float* __restrict__ cb) {
    int i = blockIdx.x * blockDim.x + threadIdx.x;   // over VOCAB*D_EMB/4
    float4 v = ((const float4*)cb)[i];
    __half h0 = __float2half_rn(v.x), h1 = __float2half_rn(v.y);
    __half h2 = __float2half_rn(v.z), h3 = __float2half_rn(v.w);
    __half l0 = __float2half_rn(v.x - __half2float(h0));
    __half l1 = __float2half_rn(v.y - __half2float(h1));
    __half l2 = __float2half_rn(v.z - __half2float(h2));
    __half l3 = __float2half_rn(v.w - __half2float(h3));
    ((__half2*)g_Ch)[i * 2 + 0] = __halves2half2(h0, h1);
    ((__half2*)g_Ch)[i * 2 + 1] = __halves2half2(h2, h3);
    ((__half2*)g_Cl)[i * 2 + 0] = __halves2half2(l0, l1);
    ((__half2*)g_Cl)[i * 2 + 1] = __halves2half2(l2, l3);
}

// ---------------------------------------------------------------------------
// Kernel 3: X = H @ W2cat + bias ; epilogue splits into f16 hi/lo
// ---------------------------------------------------------------------------
#define BM 128
#define BN 128
#define BK 16
__global__ __launch_bounds__(256) void embed_gemm_kernel(
    const float* __restrict__ Ws2, const float* __restrict__ bs2,
    const float* __restrict__ Wf2, const float* __restrict__ bf2) {
    __shared__ float As[BK][BM];
    __shared__ float Bs[BK][BN];
    int tid = threadIdx.x;
    int tx = tid & 15, ty = tid >> 4;
    int m0 = blockIdx.x * BM;
    int n0 = blockIdx.y * BN;

    u64 acc[8][4];
#pragma unroll
    for (int i = 0; i < 8; i++)
#pragma unroll
        for (int j = 0; j < 4; j++) acc[i][j] = 0ull;

    for (int kt = 0; kt < KH / BK; kt++) {
#pragma unroll
        for (int e = 0; e < 2; e++) {
            int s = tid * 2 + e;
            int m = s >> 2, kq = s & 3;
            float4 v = *(const float4*)(g_H + (size_t)(m0 + m) * KH + kt * BK + kq * 4);
            As[kq * 4 + 0][m] = v.x; As[kq * 4 + 1][m] = v.y;
            As[kq * 4 + 2][m] = v.z; As[kq * 4 + 3][m] = v.w;
        }
#pragma unroll
        for (int e = 0; e < 2; e++) {
            int s = tid * 2 + e;
            int k = s >> 5;
            int n = (s & 31) * 4;
            int kg = kt * BK + k;
            const float* src = (kg < HID) ? (Ws2 + (size_t)kg * D_EMB)
                                          : (Wf2 + (size_t)(kg - HID) * D_EMB);
            *(float4*)&Bs[k][n] = *(const float4*)(src + n0 + n);
        }
        __syncthreads();
#pragma unroll
        for (int k = 0; k < BK; k++) {
            ulonglong2 p0 = *(const ulonglong2*)&Bs[k][tx * 8];
            ulonglong2 p1 = *(const ulonglong2*)&Bs[k][tx * 8 + 4];
            u64 b[4] = {p0.x, p0.y, p1.x, p1.y};
            float4 a0 = *(const float4*)&As[k][ty * 8];
            float4 a1 = *(const float4*)&As[k][ty * 8 + 4];
            u64 ad[8];
            ad[0] = pack2(a0.x, a0.x); ad[1] = pack2(a0.y, a0.y);
            ad[2] = pack2(a0.z, a0.z); ad[3] = pack2(a0.w, a0.w);
            ad[4] = pack2(a1.x, a1.x); ad[5] = pack2(a1.y, a1.y);
            ad[6] = pack2(a1.z, a1.z); ad[7] = pack2(a1.w, a1.w);
#pragma unroll
            for (int i = 0; i < 8; i++)
#pragma unroll
                for (int j = 0; j < 4; j++)
                    acc[i][j] = fma2(ad[i], b[j], acc[i][j]);
        }
        __syncthreads();
    }
#pragma unroll
    for (int j = 0; j < 4; j++) {
        int c = n0 + tx * 8 + j * 2;
        float bb0 = bs2[c] + bf2[c];
        float bb1 = bs2[c + 1] + bf2[c + 1];
#pragma unroll
        for (int i = 0; i < 8; i++) {
            float lo, hi; unpack2(acc[i][j], lo, hi);
            float x0 = lo + bb0, x1 = hi + bb1;
            __half h0 = __float2half_rn(x0), h1 = __float2half_rn(x1);
            __half l0 = __float2half_rn(x0 - __half2float(h0));
            __half l1 = __float2half_rn(x1 - __half2float(h1));
            size_t o = (size_t)(m0 + ty * 8 + i) * D_EMB + c;
            *(__half2*)(g_Xh + o) = __halves2half2(h0, h1);
            *(__half2*)(g_Xl + o) = __halves2half2(l0, l1);
        }
    }
}

// ---------------------------------------------------------------------------
// Kernel 4: VQ via mma.sync f16-split HMMA.
// Block: 128 rows x full vocab; dist = ||c||^2 - 2(Xh.Ch + Xh.Cl + Xl.Ch).
// ---------------------------------------------------------------------------
#define VBM 128
#define VBN 128
#define VBK 64                    // halves per k-stage (128B rows)
#define NKT (D_EMB / VBK)         // 12
#define NVT (VOCAB / VBN)         // 32
#define NTILE (NVT * NKT)         // 384

#define SOFF_CSQ 0
#define SOFF_TILES 16384
#define ARR_SZ 16384              // one 128x64-half array
#define STG_SZ (4 * ARR_SZ)       // AH | AL | BH | BL
#define VQ_SMEM (SOFF_TILES + 2 * STG_SZ)   // 147456

// swizzled smem addr: 128B rows, 16B chunks, chunk ^= row&7
__device__ __forceinline__ uint32_t sw_addr(uint32_t base, int row, int ch) {
    return base + row * 128 + ((ch ^ (row & 7)) << 4);
}
// warp-collective x4 ldmatrix covering (row0..row0+15, ch0..ch0+1)
__device__ __forceinline__ void frag_ld(uint32_t* r, uint32_t tbase, int row0, int ch0, int lane) {
    int g = lane >> 3;
    int row = row0 + ((g & 1) << 3) + (lane & 7);
    int ch = ch0 + (g >> 1);
    ldsm4(r, sw_addr(tbase, row, ch));
}

__device__ __forceinline__ void fill_stage(uint32_t sbase, int m0, int v0, int kc, int tid) {
#pragma unroll
    for (int it = 0; it < 16; it++) {
        int t = it * 256 + tid;          // 0..4095
        int arr = t >> 10;               // 0:Xh 1:Xl 2:Ch 3:Cl
        int idx = t & 1023;
        int row = idx >> 3, c = idx & 7;
        const __half* src;
        if (arr == 0)      src = g_Xh + (size_t)(m0 + row) * D_EMB + kc + c * 8;
        else if (arr == 1) src = g_Xl + (size_t)(m0 + row) * D_EMB + kc + c * 8;
        else if (arr == 2) src = g_Ch + (size_t)(v0 + row) * D_EMB + kc + c * 8;
        else               src = g_Cl + (size_t)(v0 + row) * D_EMB + kc + c * 8;
        uint32_t dst = sw_addr(sbase + arr * ARR_SZ, row, c);
        cp_async16(dst, src);
    }
}

__global__ __launch_bounds__(256, 1) void vq_hmma_kernel(const float* __restrict__ cb,
                                                         float* __restrict__ out_tok,
                                                         float* __restrict__ out_q) {
    extern __shared__ char sm[];
    uint32_t smu = smem_to_u32(sm);
    int tid = threadIdx.x;
    int lane = tid & 31, wid = tid >> 5;
    int m0 = blockIdx.x * VBM;
    int wm = (wid & 3) * 32;        // warp row offset
    int wn = (wid >> 2) * 64;       // warp col offset (within 128)
    int wnid = wid >> 2;

    // stage csq into smem
    for (int i = tid; i < VOCAB / 4; i += 256)
        ((float4*)(sm + SOFF_CSQ))[i] = ((const float4*)g_csq)[i];

    // prefetch tile 0
    fill_stage(smu + SOFF_TILES, m0, 0, 0, tid);
    CP_COMMIT();
    CP_WAIT0();
    __syncthreads();

    float bv[4]; int bi[4];
#pragma unroll
    for (int i = 0; i < 4; i++) { bv[i] = 3.4e38f; bi[i] = 0; }

    const float* scq = (const float*)(sm + SOFF_CSQ);
    int q = lane >> 2, p = lane & 3;

    for (int vt = 0; vt < NVT; vt++) {
        float acc[2][8][4];
#pragma unroll
        for (int mi = 0; mi < 2; mi++)
#pragma unroll
            for (int nj = 0; nj < 8; nj++)
#pragma unroll
                for (int e = 0; e < 4; e++) acc[mi][nj][e] = 0.f;

        for (int kt = 0; kt < NKT; kt++) {
            int g = vt * NKT + kt;
            int ng = g + 1;
            if (ng < NTILE) {
                int nvt = ng / NKT, nkt = ng - nvt * NKT;
                fill_stage(smu + SOFF_TILES + (ng & 1) * STG_SZ, m0, nvt * VBN, nkt * VBK, tid);
            }
            CP_COMMIT();

            uint32_t sb = smu + SOFF_TILES + (g & 1) * STG_SZ;
            uint32_t AH = sb, AL = sb + ARR_SZ, BH = sb + 2 * ARR_SZ, BL = sb + 3 * ARR_SZ;
#pragma unroll
            for (int ks = 0; ks < 4; ks++) {
                int ch0 = ks * 2;
                uint32_t ah[2][4], al[2][4], bh[4][4], bl[4][4];
#pragma unroll
                for (int mi = 0; mi < 2; mi++) {
                    frag_ld(ah[mi], AH, wm + mi * 16, ch0, lane);
                    frag_ld(al[mi], AL, wm + mi * 16, ch0, lane);
                }
#pragma unroll
                for (int nj = 0; nj < 4; nj++) {
                    frag_ld(bh[nj], BH, wn + nj * 16, ch0, lane);
                    frag_ld(bl[nj], BL, wn + nj * 16, ch0, lane);
                }
#pragma unroll
                for (int mi = 0; mi < 2; mi++)
#pragma unroll
                    for (int nj = 0; nj < 4; nj++)
#pragma unroll
                        for (int h = 0; h < 2; h++) {
                            uint32_t bhf[2] = { bh[nj][h], bh[nj][h + 2] };
                            uint32_t blf[2] = { bl[nj][h], bl[nj][h + 2] };
                            float* c = acc[mi][nj * 2 + h];
                            mma16816(c, ah[mi], bhf);
                            mma16816(c, ah[mi], blf);
                            mma16816(c, al[mi], bhf);
                        }
            }
            CP_WAIT0();
            __syncthreads();
        }

        // fold this vocab tile into running argmin
#pragma unroll
        for (int mi = 0; mi < 2; mi++)
#pragma unroll
            for (int nj = 0; nj < 4; nj++)
#pragma unroll
                for (int h = 0; h < 2; h++) {
                    int n = vt * VBN + wn + nj * 16 + h * 8 + p * 2;
                    const float* c = acc[mi][nj * 2 + h];
                    float cs0 = scq[n], cs1 = scq[n + 1];
                    float d;
                    d = fmaf(-2.f, c[0], cs0);
                    if (d < bv[mi * 2 + 0] || (d == bv[mi * 2 + 0] && n < bi[mi * 2 + 0])) { bv[mi * 2 + 0] = d; bi[mi * 2 + 0] = n; }
                    d = fmaf(-2.f, c[1], cs1);
                    if (d < bv[mi * 2 + 0] || (d == bv[mi * 2 + 0] && n + 1 < bi[mi * 2 + 0])) { bv[mi * 2 + 0] = d; bi[mi * 2 + 0] = n + 1; }
                    d = fmaf(-2.f, c[2], cs0);
                    if (d < bv[mi * 2 + 1] || (d == bv[mi * 2 + 1] && n < bi[mi * 2 + 1])) { bv[mi * 2 + 1] = d; bi[mi * 2 + 1] = n; }
                    d = fmaf(-2.f, c[3], cs1);
                    if (d < bv[mi * 2 + 1] || (d == bv[mi * 2 + 1] && n + 1 < bi[mi * 2 + 1])) { bv[mi * 2 + 1] = d; bi[mi * 2 + 1] = n + 1; }
                }
    }

    // intra-warp reduction over lanes sharing q (p = 0..3)
#pragma unroll
    for (int i = 0; i < 4; i++) {
        float v = bv[i]; int ix = bi[i];
#pragma unroll
        for (int off = 1; off <= 2; off <<= 1) {
            float ov = __shfl_xor_sync(0xffffffffu, v, off);
            int   oi = __shfl_xor_sync(0xffffffffu, ix, off);
            if (ov < v || (ov == v && oi < ix)) { v = ov; ix = oi; }
        }
        bv[i] = v; bi[i] = ix;
    }
    __syncthreads();      // csq region dead -> reuse for reduction
    float* s_rv = (float*)sm;
    int*   s_ri = (int*)(sm + 1024);
    int*   s_tok = (int*)(sm + 2048);
    if (p == 0) {
#pragma unroll
        for (int i = 0; i < 4; i++) {
            int row = wm + ((i >> 1) << 4) + ((i & 1) << 3) + q;
            s_rv[row * 2 + wnid] = bv[i];
            s_ri[row * 2 + wnid] = bi[i];
        }
    }
    __syncthreads();
    if (tid < VBM) {
        float v0 = s_rv[tid * 2], v1 = s_rv[tid * 2 + 1];
        int i0 = s_ri[tid * 2], i1 = s_ri[tid * 2 + 1];
        int ix = (v1 < v0 || (v1 == v0 && i1 < i0)) ? i1 : i0;
        s_tok[tid] = ix;
        out_tok[m0 + tid] = (float)ix;
    }
    __syncthreads();
    for (int s2 = tid; s2 < VBM * (D_EMB / 4); s2 += 256) {
        int r = s2 / (D_EMB / 4);
        int cc = (s2 % (D_EMB / 4)) * 4;
        float4 v = *(const float4*)(cb + (size_t)s_tok[r] * D_EMB + cc);
        *(float4*)(out_q + (size_t)(m0 + r) * D_EMB + cc) = v;
    }
}

// ---------------------------------------------------------------------------
extern "C" void kernel_launch(void* const* d_in, const int* in_sizes, int n_in,
                              void* d_out, int out_size) {
    const float* coords = (const float*)d_in[0];
    const float* feats  = (const float*)d_in[1];
    const float* Ws1 = (const float*)d_in[2];
    const float* bs1 = (const float*)d_in[3];
    const float* Ws2 = (const float*)d_in[4];
    const float* bs2 = (const float*)d_in[5];
    const float* Wf1 = (const float*)d_in[6];
    const float* bf1 = (const float*)d_in[7];
    const float* Wf2 = (const float*)d_in[8];
    const float* bf2 = (const float*)d_in[9];
    const float* cb  = (const float*)d_in[10];

    float* outf    = (float*)d_out;
    float* out_tok = outf;               // tokens [32768] as float
    float* out_q   = outf + M_TOTAL;     // quantized [32768, 768]

    static bool attr_set = false;
    if (!attr_set) {
        cudaFuncSetAttribute(vq_hmma_kernel, cudaFuncAttributeMaxDynamicSharedMemorySize, VQ_SMEM);
        attr_set = true;
    }

    hidden_kernel<<<M_TOTAL, 256>>>(coords, feats, Ws1, bs1, Wf1, bf1);
    csq_kernel<<<VOCAB / 8, 256>>>(cb);
    split_cb_kernel<<<(VOCAB * D_EMB / 4) / 256, 256>>>(cb);
    dim3 g2(M_TOTAL / BM, D_EMB / BN);
    embed_gemm_kernel<<<g2, 256>>>(Ws2, bs2, Wf2, bf2);
    vq_hmma_kernel<<<M_TOTAL / VBM, 256, VQ_SMEM>>>(cb, out_tok, out_q);
}

// round 5
// speedup vs baseline: 6.1615x; 1.9827x over previous
#include <cuda_runtime.h>
#include <cuda_fp16.h>
#include <cstdint>

#define M_TOTAL 32768      // B*N
#define D_EMB   768
#define VOCAB   4096
#define HID     128
#define KH      256

// ---------------- scratch globals (no cudaMalloc allowed) -------------------
__device__ float g_H[M_TOTAL * KH];
__device__ __align__(16) __half g_Xh[(size_t)M_TOTAL * D_EMB];
__device__ __align__(16) __half g_Ch[(size_t)VOCAB * D_EMB];
__device__ __align__(16) float g_X[(size_t)M_TOTAL * D_EMB];
__device__ float g_csq[VOCAB];
__device__ int g_ccnt[M_TOTAL];
__device__ unsigned short g_cidx[M_TOTAL * 16];

typedef unsigned long long u64;

// ---------------- f32x2 helpers (embed gemm) --------------------------------
__device__ __forceinline__ u64 pack2(float x, float y) {
    u64 r; unsigned xi = __float_as_uint(x), yi = __float_as_uint(y);
    asm("mov.b64 %0, {%1, %2};" : "=l"(r) : "r"(xi), "r"(yi));
    return r;
}
__device__ __forceinline__ void unpack2(u64 v, float& x, float& y) {
    unsigned xi, yi;
    asm("mov.b64 {%0, %1}, %2;" : "=r"(xi), "=r"(yi) : "l"(v));
    x = __uint_as_float(xi); y = __uint_as_float(yi);
}
__device__ __forceinline__ u64 fma2(u64 a, u64 b, u64 c) {
    u64 d; asm("fma.rn.f32x2 %0, %1, %2, %3;" : "=l"(d) : "l"(a), "l"(b), "l"(c));
    return d;
}

// ---------------- mma.sync helpers ------------------------------------------
__device__ __forceinline__ uint32_t smem_to_u32(const void* p) {
    uint32_t a;
    asm("{ .reg .u64 t; cvta.to.shared.u64 t, %1; cvt.u32.u64 %0, t; }" : "=r"(a) : "l"(p));
    return a;
}
__device__ __forceinline__ void ldsm4(uint32_t* r, uint32_t addr) {
    asm volatile("ldmatrix.sync.aligned.m8n8.x4.shared.b16 {%0,%1,%2,%3}, [%4];"
        : "=r"(r[0]), "=r"(r[1]), "=r"(r[2]), "=r"(r[3]) : "r"(addr));
}
__device__ __forceinline__ void mma16816(float* c, const uint32_t* a, const uint32_t* b) {
    asm volatile("mma.sync.aligned.m16n8k16.row.col.f32.f16.f16.f32 "
        "{%0,%1,%2,%3}, {%4,%5,%6,%7}, {%8,%9}, {%0,%1,%2,%3};"
        : "+f"(c[0]), "+f"(c[1]), "+f"(c[2]), "+f"(c[3])
        : "r"(a[0]), "r"(a[1]), "r"(a[2]), "r"(a[3]), "r"(b[0]), "r"(b[1]));
}
__device__ __forceinline__ void cp_async16(uint32_t dst, const void* src) {
    asm volatile("cp.async.cg.shared.global [%0], [%1], 16;" :: "r"(dst), "l"(src) : "memory");
}
#define CP_COMMIT() asm volatile("cp.async.commit_group;" ::: "memory")
#define CP_WAIT0()  asm volatile("cp.async.wait_group 0;" ::: "memory")

// ---------------------------------------------------------------------------
// Kernel 1: hidden activations
// ---------------------------------------------------------------------------
__global__ void hidden_kernel(const float* __restrict__ coords,
                              const float* __restrict__ feats,
                              const float* __restrict__ Ws1, const float* __restrict__ bs1,
                              const float* __restrict__ Wf1, const float* __restrict__ bf1) {
    int t = blockIdx.x * blockDim.x + threadIdx.x;
    int m = t >> 8;
    int j = t & 255;
    float acc;
    if (j < HID) {
        float c0 = coords[m * 2 + 0];
        float c1 = coords[m * 2 + 1];
        acc = bs1[j] + c0 * Ws1[j] + c1 * Ws1[HID + j];
    } else {
        int jj = j - HID;
        acc = bf1[jj];
#pragma unroll
        for (int i = 0; i < 10; i++)
            acc += feats[m * 10 + i] * Wf1[i * HID + jj];
    }
    g_H[t] = fmaxf(acc, 0.0f);
}

// ---------------------------------------------------------------------------
// Kernel 2: codebook squared norms
// ---------------------------------------------------------------------------
__global__ void csq_kernel(const float* __restrict__ cb) {
    int w = (blockIdx.x * blockDim.x + threadIdx.x) >> 5;
    int lane = threadIdx.x & 31;
    if (w >= VOCAB) return;
    const float* row = cb + (size_t)w * D_EMB;
    float s = 0.f;
    for (int i = lane; i < D_EMB; i += 32) { float v = row[i]; s += v * v; }
#pragma unroll
    for (int o = 16; o; o >>= 1) s += __shfl_down_sync(0xffffffffu, s, o);
    if (lane == 0) g_csq[w] = s;
}

// ---------------------------------------------------------------------------
// Kernel 2b: codebook -> f16 (hi only)
// ---------------------------------------------------------------------------
__global__ void split_cb_kernel(const float* __restrict__ cb) {
    int i = blockIdx.x * blockDim.x + threadIdx.x;   // over VOCAB*D_EMB/4
    float4 v = ((const float4*)cb)[i];
    ((__half2*)g_Ch)[i * 2 + 0] = __halves2half2(__float2half_rn(v.x), __float2half_rn(v.y));
    ((__half2*)g_Ch)[i * 2 + 1] = __halves2half2(__float2half_rn(v.z), __float2half_rn(v.w));
}

// ---------------------------------------------------------------------------
// Kernel 3: X = H @ W2cat + bias ; writes fp32 X and f16 Xh
// ---------------------------------------------------------------------------
#define BM 128
#define BN 128
#define BK 16
__global__ __launch_bounds__(256) void embed_gemm_kernel(
    const float* __restrict__ Ws2, const float* __restrict__ bs2,
    const float* __restrict__ Wf2, const float* __restrict__ bf2) {
    __shared__ float As[BK][BM];
    __shared__ float Bs[BK][BN];
    int tid = threadIdx.x;
    int tx = tid & 15, ty = tid >> 4;
    int m0 = blockIdx.x * BM;
    int n0 = blockIdx.y * BN;

    u64 acc[8][4];
#pragma unroll
    for (int i = 0; i < 8; i++)
#pragma unroll
        for (int j = 0; j < 4; j++) acc[i][j] = 0ull;

    for (int kt = 0; kt < KH / BK; kt++) {
#pragma unroll
        for (int e = 0; e < 2; e++) {
            int s = tid * 2 + e;
            int m = s >> 2, kq = s & 3;
            float4 v = *(const float4*)(g_H + (size_t)(m0 + m) * KH + kt * BK + kq * 4);
            As[kq * 4 + 0][m] = v.x; As[kq * 4 + 1][m] = v.y;
            As[kq * 4 + 2][m] = v.z; As[kq * 4 + 3][m] = v.w;
        }
#pragma unroll
        for (int e = 0; e < 2; e++) {
            int s = tid * 2 + e;
            int k = s >> 5;
            int n = (s & 31) * 4;
            int kg = kt * BK + k;
            const float* src = (kg < HID) ? (Ws2 + (size_t)kg * D_EMB)
                                          : (Wf2 + (size_t)(kg - HID) * D_EMB);
            *(float4*)&Bs[k][n] = *(const float4*)(src + n0 + n);
        }
        __syncthreads();
#pragma unroll
        for (int k = 0; k < BK; k++) {
            ulonglong2 p0 = *(const ulonglong2*)&Bs[k][tx * 8];
            ulonglong2 p1 = *(const ulonglong2*)&Bs[k][tx * 8 + 4];
            u64 b[4] = {p0.x, p0.y, p1.x, p1.y};
            float4 a0 = *(const float4*)&As[k][ty * 8];
            float4 a1 = *(const float4*)&As[k][ty * 8 + 4];
            u64 ad[8];
            ad[0] = pack2(a0.x, a0.x); ad[1] = pack2(a0.y, a0.y);
            ad[2] = pack2(a0.z, a0.z); ad[3] = pack2(a0.w, a0.w);
            ad[4] = pack2(a1.x, a1.x); ad[5] = pack2(a1.y, a1.y);
            ad[6] = pack2(a1.z, a1.z); ad[7] = pack2(a1.w, a1.w);
#pragma unroll
            for (int i = 0; i < 8; i++)
#pragma unroll
                for (int j = 0; j < 4; j++)
                    acc[i][j] = fma2(ad[i], b[j], acc[i][j]);
        }
        __syncthreads();
    }
#pragma unroll
    for (int j = 0; j < 4; j++) {
        int c = n0 + tx * 8 + j * 2;
        float bb0 = bs2[c] + bf2[c];
        float bb1 = bs2[c + 1] + bf2[c + 1];
#pragma unroll
        for (int i = 0; i < 8; i++) {
            float lo, hi; unpack2(acc[i][j], lo, hi);
            float x0 = lo + bb0, x1 = hi + bb1;
            size_t o = (size_t)(m0 + ty * 8 + i) * D_EMB + c;
            *(float2*)(g_X + o) = make_float2(x0, x1);
            *(__half2*)(g_Xh + o) = __halves2half2(__float2half_rn(x0), __float2half_rn(x1));
        }
    }
}

// ---------------------------------------------------------------------------
// Kernel 4 (pass 1): approx VQ via 1-term HMMA (Xh.Ch), best-2 candidate
// collection per owner thread, margin filter -> g_cidx/g_ccnt.
// ---------------------------------------------------------------------------
#define VBM 128
#define VBN 128
#define VBK 64                    // halves per k-stage (128B rows)
#define NKT (D_EMB / VBK)         // 12
#define NVT (VOCAB / VBN)         // 32
#define NTILE (NVT * NKT)         // 384
#define MARGIN 0.5f

#define SOFF_CSQ 0
#define SOFF_TILES 16384
#define ARR_SZ 16384              // one 128x64-half array
#define STG_SZ (2 * ARR_SZ)       // AH | BH
#define VQ_SMEM (SOFF_TILES + 2 * STG_SZ)   // 81920

__device__ __forceinline__ uint32_t sw_addr(uint32_t base, int row, int ch) {
    return base + row * 128 + ((ch ^ (row & 7)) << 4);
}
__device__ __forceinline__ void frag_ld(uint32_t* r, uint32_t tbase, int row0, int ch0, int lane) {
    int g = lane >> 3;
    int row = row0 + ((g & 1) << 3) + (lane & 7);
    int ch = ch0 + (g >> 1);
    ldsm4(r, sw_addr(tbase, row, ch));
}

__device__ __forceinline__ void fill_stage(uint32_t sbase, int m0, int v0, int kc, int tid) {
#pragma unroll
    for (int it = 0; it < 8; it++) {
        int t = it * 256 + tid;          // 0..2047
        int arr = t >> 10;               // 0:Xh 1:Ch
        int idx = t & 1023;
        int row = idx >> 3, c = idx & 7;
        const __half* src = (arr == 0)
            ? g_Xh + (size_t)(m0 + row) * D_EMB + kc + c * 8
            : g_Ch + (size_t)(v0 + row) * D_EMB + kc + c * 8;
        cp_async16(sw_addr(sbase + arr * ARR_SZ, row, c), src);
    }
}

__global__ __launch_bounds__(256, 2) void vq_pass1_kernel() {
    extern __shared__ char sm[];
    uint32_t smu = smem_to_u32(sm);
    int tid = threadIdx.x;
    int lane = tid & 31, wid = tid >> 5;
    int m0 = blockIdx.x * VBM;
    int wm = (wid & 3) * 32;        // warp row offset
    int wn = (wid >> 2) * 64;       // warp col offset (within 128)
    int wnid = wid >> 2;
    int q = lane >> 2, p = lane & 3;

    // stage csq into smem
    for (int i = tid; i < VOCAB / 4; i += 256)
        ((float4*)(sm + SOFF_CSQ))[i] = ((const float4*)g_csq)[i];

    fill_stage(smu + SOFF_TILES, m0, 0, 0, tid);
    CP_COMMIT();
    CP_WAIT0();
    __syncthreads();

    // per-thread best-2 per row-slot (4 slots)
    float v0[4], v1[4]; int i0[4], i1[4];
#pragma unroll
    for (int i = 0; i < 4; i++) { v0[i] = 3.4e38f; v1[i] = 3.4e38f; i0[i] = 0; i1[i] = 0; }

    const float* scq = (const float*)(sm + SOFF_CSQ);

    for (int vt = 0; vt < NVT; vt++) {
        float acc[2][8][4];
#pragma unroll
        for (int mi = 0; mi < 2; mi++)
#pragma unroll
            for (int nj = 0; nj < 8; nj++)
#pragma unroll
                for (int e = 0; e < 4; e++) acc[mi][nj][e] = 0.f;

        for (int kt = 0; kt < NKT; kt++) {
            int g = vt * NKT + kt;
            int ng = g + 1;
            if (ng < NTILE) {
                int nvt = ng / NKT, nkt = ng - nvt * NKT;
                fill_stage(smu + SOFF_TILES + (ng & 1) * STG_SZ, m0, nvt * VBN, nkt * VBK, tid);
            }
            CP_COMMIT();

            uint32_t sb = smu + SOFF_TILES + (g & 1) * STG_SZ;
            uint32_t AH = sb, BH = sb + ARR_SZ;
#pragma unroll
            for (int ks = 0; ks < 4; ks++) {
                int ch0 = ks * 2;
                uint32_t ah[2][4], bh[4][4];
#pragma unroll
                for (int mi = 0; mi < 2; mi++) frag_ld(ah[mi], AH, wm + mi * 16, ch0, lane);
#pragma unroll
                for (int nj = 0; nj < 4; nj++) frag_ld(bh[nj], BH, wn + nj * 16, ch0, lane);
#pragma unroll
                for (int mi = 0; mi < 2; mi++)
#pragma unroll
                    for (int nj = 0; nj < 4; nj++)
#pragma unroll
                        for (int h = 0; h < 2; h++) {
                            uint32_t bf[2] = { bh[nj][h], bh[nj][h + 2] };
                            mma16816(acc[mi][nj * 2 + h], ah[mi], bf);
                        }
            }
            CP_WAIT0();
            __syncthreads();
        }

        // fold: insert dists into per-slot best-2
#pragma unroll
        for (int mi = 0; mi < 2; mi++)
#pragma unroll
            for (int nj = 0; nj < 4; nj++)
#pragma unroll
                for (int h = 0; h < 2; h++) {
                    int n = vt * VBN + wn + nj * 16 + h * 8 + p * 2;
                    const float* c = acc[mi][nj * 2 + h];
                    float cs0 = scq[n], cs1 = scq[n + 1];
#pragma unroll
                    for (int e = 0; e < 4; e++) {
                        int s = mi * 2 + (e >> 1);
                        int nn = n + (e & 1);
                        float d = fmaf(-2.f, c[e], (e & 1) ? cs1 : cs0);
                        if (d < v1[s]) {
                            if (d < v0[s]) { v1[s] = v0[s]; i1[s] = i0[s]; v0[s] = d; i0[s] = nn; }
                            else           { v1[s] = d; i1[s] = nn; }
                        }
                    }
                }
    }

    // dump best-2 sets: 8 owner threads x 2 = 16 candidates per row
    __syncthreads();
    float* s_cval = (float*)sm;                       // [128][16]
    unsigned short* s_cidx = (unsigned short*)(sm + 8192);  // [128][16]
    int bslot = (wnid * 4 + p) * 2;
#pragma unroll
    for (int s = 0; s < 4; s++) {
        int row = wm + ((s >> 1) << 4) + ((s & 1) << 3) + q;
        s_cval[row * 16 + bslot] = v0[s];
        s_cidx[row * 16 + bslot] = (unsigned short)i0[s];
        s_cval[row * 16 + bslot + 1] = v1[s];
        s_cidx[row * 16 + bslot + 1] = (unsigned short)i1[s];
    }
    __syncthreads();
    if (tid < VBM) {
        int row = tid;
        float best = s_cval[row * 16]; int bj = 0;
#pragma unroll
        for (int j = 1; j < 16; j++) {
            float v = s_cval[row * 16 + j];
            if (v < best) { best = v; bj = j; }
        }
        int cnt = 0;
        g_cidx[(size_t)(m0 + row) * 16 + cnt++] = s_cidx[row * 16 + bj];
#pragma unroll
        for (int j = 0; j < 16; j++) {
            if (j == bj) continue;
            if (s_cval[row * 16 + j] < best + MARGIN && cnt < 16)
                g_cidx[(size_t)(m0 + row) * 16 + cnt++] = s_cidx[row * 16 + j];
        }
        g_ccnt[m0 + row] = cnt;
    }
}

// ---------------------------------------------------------------------------
// Kernel 5 (pass 2): exact fp32 refine over candidates; write tokens + gather
// ---------------------------------------------------------------------------
__global__ __launch_bounds__(256) void vq_refine_kernel(const float* __restrict__ cb,
                                                        float* __restrict__ out_tok,
                                                        float* __restrict__ out_q) {
    int lane = threadIdx.x & 31, wid = threadIdx.x >> 5;
    int row = blockIdx.x * 8 + wid;

    float x[24];
#pragma unroll
    for (int j = 0; j < 24; j++) x[j] = g_X[(size_t)row * D_EMB + j * 32 + lane];

    int cnt = g_ccnt[row];
    float best = 3.4e38f; int bi = VOCAB;
    for (int ci = 0; ci < cnt; ci++) {
        int c = g_cidx[(size_t)row * 16 + ci];
        const float* crow = cb + (size_t)c * D_EMB;
        float dot = 0.f;
#pragma unroll
        for (int j = 0; j < 24; j++) dot = fmaf(x[j], crow[j * 32 + lane], dot);
#pragma unroll
        for (int o = 16; o; o >>= 1) dot += __shfl_xor_sync(0xffffffffu, dot, o);
        float d = g_csq[c] - 2.f * dot;
        if (d < best || (d == best && c < bi)) { best = d; bi = c; }
    }
    if (lane == 0) out_tok[row] = (float)bi;
    const float4* src = (const float4*)(cb + (size_t)bi * D_EMB);
    float4* dst = (float4*)(out_q + (size_t)row * D_EMB);
#pragma unroll
    for (int j = 0; j < 6; j++) dst[lane + j * 32] = src[lane + j * 32];
}

// ---------------------------------------------------------------------------
extern "C" void kernel_launch(void* const* d_in, const int* in_sizes, int n_in,
                              void* d_out, int out_size) {
    const float* coords = (const float*)d_in[0];
    const float* feats  = (const float*)d_in[1];
    const float* Ws1 = (const float*)d_in[2];
    const float* bs1 = (const float*)d_in[3];
    const float* Ws2 = (const float*)d_in[4];
    const float* bs2 = (const float*)d_in[5];
    const float* Wf1 = (const float*)d_in[6];
    const float* bf1 = (const float*)d_in[7];
    const float* Wf2 = (const float*)d_in[8];
    const float* bf2 = (const float*)d_in[9];
    const float* cb  = (const float*)d_in[10];

    float* outf    = (float*)d_out;
    float* out_tok = outf;               // tokens [32768] as float
    float* out_q   = outf + M_TOTAL;     // quantized [32768, 768]

    static bool attr_set = false;
    if (!attr_set) {
        cudaFuncSetAttribute(vq_pass1_kernel, cudaFuncAttributeMaxDynamicSharedMemorySize, VQ_SMEM);
        attr_set = true;
    }

    hidden_kernel<<<M_TOTAL, 256>>>(coords, feats, Ws1, bs1, Wf1, bf1);
    csq_kernel<<<VOCAB / 8, 256>>>(cb);
    split_cb_kernel<<<(VOCAB * D_EMB / 4) / 256, 256>>>(cb);
    dim3 g2(M_TOTAL / BM, D_EMB / BN);
    embed_gemm_kernel<<<g2, 256>>>(Ws2, bs2, Wf2, bf2);
    vq_pass1_kernel<<<M_TOTAL / VBM, 256, VQ_SMEM>>>();
    vq_refine_kernel<<<M_TOTAL / 8, 256>>>(cb, out_tok, out_q);
}

// round 6
// speedup vs baseline: 7.7250x; 1.2537x over previous
#include <cuda_runtime.h>
#include <cuda_fp16.h>
#include <cstdint>

#define M_TOTAL 32768      // B*N
#define D_EMB   768
#define VOCAB   4096
#define HID     128
#define KH      256

// ---------------- scratch globals (no cudaMalloc allowed) -------------------
__device__ __align__(16) __half g_Hh[(size_t)M_TOTAL * KH];
__device__ __align__(16) __half g_Hl[(size_t)M_TOTAL * KH];
__device__ __align__(16) __half g_WhT[(size_t)D_EMB * KH];   // [n][k]
__device__ __align__(16) __half g_WlT[(size_t)D_EMB * KH];
__device__ float g_bias[D_EMB];
__device__ __align__(16) __half g_Xh[(size_t)M_TOTAL * D_EMB];
__device__ __align__(16) __half g_Ch[(size_t)VOCAB * D_EMB];
__device__ __align__(16) float g_X[(size_t)M_TOTAL * D_EMB];
__device__ float g_csq[VOCAB];
__device__ int g_ccnt[M_TOTAL];
__device__ unsigned short g_cidx[M_TOTAL * 16];

// ---------------- mma.sync helpers ------------------------------------------
__device__ __forceinline__ uint32_t smem_to_u32(const void* p) {
    uint32_t a;
    asm("{ .reg .u64 t; cvta.to.shared.u64 t, %1; cvt.u32.u64 %0, t; }" : "=r"(a) : "l"(p));
    return a;
}
__device__ __forceinline__ void ldsm4(uint32_t* r, uint32_t addr) {
    asm volatile("ldmatrix.sync.aligned.m8n8.x4.shared.b16 {%0,%1,%2,%3}, [%4];"
        : "=r"(r[0]), "=r"(r[1]), "=r"(r[2]), "=r"(r[3]) : "r"(addr));
}
__device__ __forceinline__ void mma16816(float* c, const uint32_t* a, const uint32_t* b) {
    asm volatile("mma.sync.aligned.m16n8k16.row.col.f32.f16.f16.f32 "
        "{%0,%1,%2,%3}, {%4,%5,%6,%7}, {%8,%9}, {%0,%1,%2,%3};"
        : "+f"(c[0]), "+f"(c[1]), "+f"(c[2]), "+f"(c[3])
        : "r"(a[0]), "r"(a[1]), "r"(a[2]), "r"(a[3]), "r"(b[0]), "r"(b[1]));
}
__device__ __forceinline__ void cp_async16(uint32_t dst, const void* src) {
    asm volatile("cp.async.cg.shared.global [%0], [%1], 16;" :: "r"(dst), "l"(src) : "memory");
}
#define CP_COMMIT() asm volatile("cp.async.commit_group;" ::: "memory")
#define CP_WAIT0()  asm volatile("cp.async.wait_group 0;" ::: "memory")

__device__ __forceinline__ uint32_t sw_addr(uint32_t base, int row, int ch) {
    return base + row * 128 + ((ch ^ (row & 7)) << 4);
}
__device__ __forceinline__ void frag_ld(uint32_t* r, uint32_t tbase, int row0, int ch0, int lane) {
    int g = lane >> 3;
    int row = row0 + ((g & 1) << 3) + (lane & 7);
    int ch = ch0 + (g >> 1);
    ldsm4(r, sw_addr(tbase, row, ch));
}

// ---------------------------------------------------------------------------
// Kernel 1: hidden activations -> f16 hi/lo
// ---------------------------------------------------------------------------
__global__ void hidden_kernel(const float* __restrict__ coords,
                              const float* __restrict__ feats,
                              const float* __restrict__ Ws1, const float* __restrict__ bs1,
                              const float* __restrict__ Wf1, const float* __restrict__ bf1) {
    int t = blockIdx.x * blockDim.x + threadIdx.x;
    int m = t >> 8;
    int j = t & 255;
    float acc;
    if (j < HID) {
        float c0 = coords[m * 2 + 0];
        float c1 = coords[m * 2 + 1];
        acc = bs1[j] + c0 * Ws1[j] + c1 * Ws1[HID + j];
    } else {
        int jj = j - HID;
        acc = bf1[jj];
#pragma unroll
        for (int i = 0; i < 10; i++)
            acc += feats[m * 10 + i] * Wf1[i * HID + jj];
    }
    acc = fmaxf(acc, 0.0f);
    __half h = __float2half_rn(acc);
    __half l = __float2half_rn(acc - __half2float(h));
    g_Hh[t] = h;
    g_Hl[t] = l;
}

// ---------------------------------------------------------------------------
// Kernel 2: codebook squared norms
// ---------------------------------------------------------------------------
__global__ void csq_kernel(const float* __restrict__ cb) {
    int w = (blockIdx.x * blockDim.x + threadIdx.x) >> 5;
    int lane = threadIdx.x & 31;
    if (w >= VOCAB) return;
    const float* row = cb + (size_t)w * D_EMB;
    float s = 0.f;
    for (int i = lane; i < D_EMB; i += 32) { float v = row[i]; s += v * v; }
#pragma unroll
    for (int o = 16; o; o >>= 1) s += __shfl_down_sync(0xffffffffu, s, o);
    if (lane == 0) g_csq[w] = s;
}

// ---------------------------------------------------------------------------
// Kernel 2b: codebook -> f16 (hi only)
// ---------------------------------------------------------------------------
__global__ void split_cb_kernel(const float* __restrict__ cb) {
    int i = blockIdx.x * blockDim.x + threadIdx.x;   // over VOCAB*D_EMB/4
    float4 v = ((const float4*)cb)[i];
    ((__half2*)g_Ch)[i * 2 + 0] = __halves2half2(__float2half_rn(v.x), __float2half_rn(v.y));
    ((__half2*)g_Ch)[i * 2 + 1] = __halves2half2(__float2half_rn(v.z), __float2half_rn(v.w));
}

// ---------------------------------------------------------------------------
// Kernel 2c: W2cat -> transposed f16 hi/lo [n][k], plus combined bias
// ---------------------------------------------------------------------------
__global__ void wsplit_kernel(const float* __restrict__ Ws2, const float* __restrict__ Wf2,
                              const float* __restrict__ bs2, const float* __restrict__ bf2) {
    int t = blockIdx.x * blockDim.x + threadIdx.x;   // 0 .. 256*768-1
    if (t < D_EMB) g_bias[t] = bs2[t] + bf2[t];
    int kg = t / D_EMB, n = t - kg * D_EMB;
    float w = (kg < HID) ? Ws2[(size_t)kg * D_EMB + n] : Wf2[(size_t)(kg - HID) * D_EMB + n];
    __half h = __float2half_rn(w);
    __half l = __float2half_rn(w - __half2float(h));
    g_WhT[(size_t)n * KH + kg] = h;
    g_WlT[(size_t)n * KH + kg] = l;
}

// ---------------------------------------------------------------------------
// Kernel 3: embed GEMM via HMMA 3-term split.
// X[m,n] = sum_k (Hh+Hl)[m,k] (Wh+Wl)[k,n] + bias  (drop Hl*Wl)
// ---------------------------------------------------------------------------
#define EARR_SZ 16384              // one 128x64-half array
#define ESTG_SZ (4 * EARR_SZ)      // AH|AL|BH|BL
#define E_SMEM (2 * ESTG_SZ)       // 131072

__device__ __forceinline__ void fill_e(uint32_t sbase, int m0, int n0, int kc, int tid) {
#pragma unroll
    for (int it = 0; it < 16; it++) {
        int t = it * 256 + tid;          // 0..4095
        int arr = t >> 10;               // 0:Hh 1:Hl 2:WhT 3:WlT
        int idx = t & 1023;
        int row = idx >> 3, c = idx & 7;
        const __half* src;
        if (arr == 0)      src = g_Hh + (size_t)(m0 + row) * KH + kc + c * 8;
        else if (arr == 1) src = g_Hl + (size_t)(m0 + row) * KH + kc + c * 8;
        else if (arr == 2) src = g_WhT + (size_t)(n0 + row) * KH + kc + c * 8;
        else               src = g_WlT + (size_t)(n0 + row) * KH + kc + c * 8;
        cp_async16(sw_addr(sbase + arr * EARR_SZ, row, c), src);
    }
}

__global__ __launch_bounds__(256, 1) void embed_hmma_kernel() {
    extern __shared__ char sm[];
    uint32_t smu = smem_to_u32(sm);
    int tid = threadIdx.x;
    int lane = tid & 31, wid = tid >> 5;
    int m0 = blockIdx.x * 128;
    int n0 = blockIdx.y * 128;
    int wm = (wid & 3) * 32;
    int wn = (wid >> 2) * 64;
    int q = lane >> 2, p = lane & 3;

    fill_e(smu, m0, n0, 0, tid);
    CP_COMMIT();
    CP_WAIT0();
    __syncthreads();

    float acc[2][8][4];
#pragma unroll
    for (int mi = 0; mi < 2; mi++)
#pragma unroll
        for (int nj = 0; nj < 8; nj++)
#pragma unroll
            for (int e = 0; e < 4; e++) acc[mi][nj][e] = 0.f;

    for (int kt = 0; kt < 4; kt++) {
        if (kt + 1 < 4)
            fill_e(smu + ((kt + 1) & 1) * ESTG_SZ, m0, n0, (kt + 1) * 64, tid);
        CP_COMMIT();

        uint32_t sb = smu + (kt & 1) * ESTG_SZ;
        uint32_t AH = sb, AL = sb + EARR_SZ, BH = sb + 2 * EARR_SZ, BL = sb + 3 * EARR_SZ;
#pragma unroll
        for (int ks = 0; ks < 4; ks++) {
            int ch0 = ks * 2;
            uint32_t ah[2][4], al[2][4], bh[4][4], bl[4][4];
#pragma unroll
            for (int mi = 0; mi < 2; mi++) {
                frag_ld(ah[mi], AH, wm + mi * 16, ch0, lane);
                frag_ld(al[mi], AL, wm + mi * 16, ch0, lane);
            }
#pragma unroll
            for (int nj = 0; nj < 4; nj++) {
                frag_ld(bh[nj], BH, wn + nj * 16, ch0, lane);
                frag_ld(bl[nj], BL, wn + nj * 16, ch0, lane);
            }
#pragma unroll
            for (int mi = 0; mi < 2; mi++)
#pragma unroll
                for (int nj = 0; nj < 4; nj++)
#pragma unroll
                    for (int h = 0; h < 2; h++) {
                        uint32_t bhf[2] = { bh[nj][h], bh[nj][h + 2] };
                        uint32_t blf[2] = { bl[nj][h], bl[nj][h + 2] };
                        float* c = acc[mi][nj * 2 + h];
                        mma16816(c, ah[mi], bhf);
                        mma16816(c, ah[mi], blf);
                        mma16816(c, al[mi], bhf);
                    }
        }
        CP_WAIT0();
        __syncthreads();
    }

    // epilogue: add bias, write fp32 X and f16 Xh
#pragma unroll
    for (int mi = 0; mi < 2; mi++)
#pragma unroll
        for (int nj = 0; nj < 4; nj++)
#pragma unroll
            for (int h = 0; h < 2; h++) {
                const float* c = acc[mi][nj * 2 + h];
                int cn = n0 + wn + nj * 16 + h * 8 + p * 2;
                float bb0 = g_bias[cn], bb1 = g_bias[cn + 1];
                int r0 = m0 + wm + mi * 16 + q;
                float x00 = c[0] + bb0, x01 = c[1] + bb1;
                float x10 = c[2] + bb0, x11 = c[3] + bb1;
                size_t o0 = (size_t)r0 * D_EMB + cn;
                size_t o1 = (size_t)(r0 + 8) * D_EMB + cn;
                *(float2*)(g_X + o0) = make_float2(x00, x01);
                *(float2*)(g_X + o1) = make_float2(x10, x11);
                *(__half2*)(g_Xh + o0) = __halves2half2(__float2half_rn(x00), __float2half_rn(x01));
                *(__half2*)(g_Xh + o1) = __halves2half2(__float2half_rn(x10), __float2half_rn(x11));
            }
}

// ---------------------------------------------------------------------------
// Kernel 4 (pass 1): approx VQ via 1-term HMMA (Xh.Ch), best-2 candidates
// ---------------------------------------------------------------------------
#define VBM 128
#define VBN 128
#define VBK 64
#define NKT (D_EMB / VBK)         // 12
#define NVT (VOCAB / VBN)         // 32
#define NTILE (NVT * NKT)         // 384
#define MARGIN 0.5f

#define SOFF_CSQ 0
#define SOFF_TILES 16384
#define ARR_SZ 16384
#define STG_SZ (2 * ARR_SZ)
#define VQ_SMEM (SOFF_TILES + 2 * STG_SZ)   // 81920

__device__ __forceinline__ void fill_stage(uint32_t sbase, int m0, int v0, int kc, int tid) {
#pragma unroll
    for (int it = 0; it < 8; it++) {
        int t = it * 256 + tid;
        int arr = t >> 10;
        int idx = t & 1023;
        int row = idx >> 3, c = idx & 7;
        const __half* src = (arr == 0)
            ? g_Xh + (size_t)(m0 + row) * D_EMB + kc + c * 8
            : g_Ch + (size_t)(v0 + row) * D_EMB + kc + c * 8;
        cp_async16(sw_addr(sbase + arr * ARR_SZ, row, c), src);
    }
}

__global__ __launch_bounds__(256, 2) void vq_pass1_kernel() {
    extern __shared__ char sm[];
    uint32_t smu = smem_to_u32(sm);
    int tid = threadIdx.x;
    int lane = tid & 31, wid = tid >> 5;
    int m0 = blockIdx.x * VBM;
    int wm = (wid & 3) * 32;
    int wn = (wid >> 2) * 64;
    int wnid = wid >> 2;
    int q = lane >> 2, p = lane & 3;

    for (int i = tid; i < VOCAB / 4; i += 256)
        ((float4*)(sm + SOFF_CSQ))[i] = ((const float4*)g_csq)[i];

    fill_stage(smu + SOFF_TILES, m0, 0, 0, tid);
    CP_COMMIT();
    CP_WAIT0();
    __syncthreads();

    float v0[4], v1[4]; int i0[4], i1[4];
#pragma unroll
    for (int i = 0; i < 4; i++) { v0[i] = 3.4e38f; v1[i] = 3.4e38f; i0[i] = 0; i1[i] = 0; }

    const float* scq = (const float*)(sm + SOFF_CSQ);

    for (int vt = 0; vt < NVT; vt++) {
        float acc[2][8][4];
#pragma unroll
        for (int mi = 0; mi < 2; mi++)
#pragma unroll
            for (int nj = 0; nj < 8; nj++)
#pragma unroll
                for (int e = 0; e < 4; e++) acc[mi][nj][e] = 0.f;

        for (int kt = 0; kt < NKT; kt++) {
            int g = vt * NKT + kt;
            int ng = g + 1;
            if (ng < NTILE) {
                int nvt = ng / NKT, nkt = ng - nvt * NKT;
                fill_stage(smu + SOFF_TILES + (ng & 1) * STG_SZ, m0, nvt * VBN, nkt * VBK, tid);
            }
            CP_COMMIT();

            uint32_t sb = smu + SOFF_TILES + (g & 1) * STG_SZ;
            uint32_t AH = sb, BH = sb + ARR_SZ;
#pragma unroll
            for (int ks = 0; ks < 4; ks++) {
                int ch0 = ks * 2;
                uint32_t ah[2][4], bh[4][4];
#pragma unroll
                for (int mi = 0; mi < 2; mi++) frag_ld(ah[mi], AH, wm + mi * 16, ch0, lane);
#pragma unroll
                for (int nj = 0; nj < 4; nj++) frag_ld(bh[nj], BH, wn + nj * 16, ch0, lane);
#pragma unroll
                for (int mi = 0; mi < 2; mi++)
#pragma unroll
                    for (int nj = 0; nj < 4; nj++)
#pragma unroll
                        for (int h = 0; h < 2; h++) {
                            uint32_t bf[2] = { bh[nj][h], bh[nj][h + 2] };
                            mma16816(acc[mi][nj * 2 + h], ah[mi], bf);
                        }
            }
            CP_WAIT0();
            __syncthreads();
        }

#pragma unroll
        for (int mi = 0; mi < 2; mi++)
#pragma unroll
            for (int nj = 0; nj < 4; nj++)
#pragma unroll
                for (int h = 0; h < 2; h++) {
                    int n = vt * VBN + wn + nj * 16 + h * 8 + p * 2;
                    const float* c = acc[mi][nj * 2 + h];
                    float cs0 = scq[n], cs1 = scq[n + 1];
#pragma unroll
                    for (int e = 0; e < 4; e++) {
                        int s = mi * 2 + (e >> 1);
                        int nn = n + (e & 1);
                        float d = fmaf(-2.f, c[e], (e & 1) ? cs1 : cs0);
                        if (d < v1[s]) {
                            if (d < v0[s]) { v1[s] = v0[s]; i1[s] = i0[s]; v0[s] = d; i0[s] = nn; }
                            else           { v1[s] = d; i1[s] = nn; }
                        }
                    }
                }
    }

    __syncthreads();
    float* s_cval = (float*)sm;                            // [128][16]
    unsigned short* s_cidx = (unsigned short*)(sm + 8192); // [128][16]
    int bslot = (wnid * 4 + p) * 2;
#pragma unroll
    for (int s = 0; s < 4; s++) {
        int row = wm + ((s >> 1) << 4) + ((s & 1) << 3) + q;
        s_cval[row * 16 + bslot] = v0[s];
        s_cidx[row * 16 + bslot] = (unsigned short)i0[s];
        s_cval[row * 16 + bslot + 1] = v1[s];
        s_cidx[row * 16 + bslot + 1] = (unsigned short)i1[s];
    }
    __syncthreads();
    if (tid < VBM) {
        int row = tid;
        float best = s_cval[row * 16]; int bj = 0;
#pragma unroll
        for (int j = 1; j < 16; j++) {
            float v = s_cval[row * 16 + j];
            if (v < best) { best = v; bj = j; }
        }
        int cnt = 0;
        g_cidx[(size_t)(m0 + row) * 16 + cnt++] = s_cidx[row * 16 + bj];
#pragma unroll
        for (int j = 0; j < 16; j++) {
            if (j == bj) continue;
            if (s_cval[row * 16 + j] < best + MARGIN && cnt < 16)
                g_cidx[(size_t)(m0 + row) * 16 + cnt++] = s_cidx[row * 16 + j];
        }
        g_ccnt[m0 + row] = cnt;
    }
}

// ---------------------------------------------------------------------------
// Kernel 5 (pass 2): exact fp32 refine; tokens + gather
// ---------------------------------------------------------------------------
__global__ __launch_bounds__(256) void vq_refine_kernel(const float* __restrict__ cb,
                                                        float* __restrict__ out_tok,
                                                        float* __restrict__ out_q) {
    int lane = threadIdx.x & 31, wid = threadIdx.x >> 5;
    int row = blockIdx.x * 8 + wid;

    float x[24];
#pragma unroll
    for (int j = 0; j < 24; j++) x[j] = g_X[(size_t)row * D_EMB + j * 32 + lane];

    int cnt = g_ccnt[row];
    float best = 3.4e38f; int bi = VOCAB;
    for (int ci = 0; ci < cnt; ci++) {
        int c = g_cidx[(size_t)row * 16 + ci];
        const float* crow = cb + (size_t)c * D_EMB;
        float dot = 0.f;
#pragma unroll
        for (int j = 0; j < 24; j++) dot = fmaf(x[j], crow[j * 32 + lane], dot);
#pragma unroll
        for (int o = 16; o; o >>= 1) dot += __shfl_xor_sync(0xffffffffu, dot, o);
        float d = g_csq[c] - 2.f * dot;
        if (d < best || (d == best && c < bi)) { best = d; bi = c; }
    }
    if (lane == 0) out_tok[row] = (float)bi;
    const float4* src = (const float4*)(cb + (size_t)bi * D_EMB);
    float4* dst = (float4*)(out_q + (size_t)row * D_EMB);
#pragma unroll
    for (int j = 0; j < 6; j++) dst[lane + j * 32] = src[lane + j * 32];
}

// ---------------------------------------------------------------------------
extern "C" void kernel_launch(void* const* d_in, const int* in_sizes, int n_in,
                              void* d_out, int out_size) {
    const float* coords = (const float*)d_in[0];
    const float* feats  = (const float*)d_in[1];
    const float* Ws1 = (const float*)d_in[2];
    const float* bs1 = (const float*)d_in[3];
    const float* Ws2 = (const float*)d_in[4];
    const float* bs2 = (const float*)d_in[5];
    const float* Wf1 = (const float*)d_in[6];
    const float* bf1 = (const float*)d_in[7];
    const float* Wf2 = (const float*)d_in[8];
    const float* bf2 = (const float*)d_in[9];
    const float* cb  = (const float*)d_in[10];

    float* outf    = (float*)d_out;
    float* out_tok = outf;               // tokens [32768] as float
    float* out_q   = outf + M_TOTAL;     // quantized [32768, 768]

    static bool attr_set = false;
    if (!attr_set) {
        cudaFuncSetAttribute(vq_pass1_kernel, cudaFuncAttributeMaxDynamicSharedMemorySize, VQ_SMEM);
        cudaFuncSetAttribute(embed_hmma_kernel, cudaFuncAttributeMaxDynamicSharedMemorySize, E_SMEM);
        attr_set = true;
    }

    hidden_kernel<<<M_TOTAL, 256>>>(coords, feats, Ws1, bs1, Wf1, bf1);
    csq_kernel<<<VOCAB / 8, 256>>>(cb);
    split_cb_kernel<<<(VOCAB * D_EMB / 4) / 256, 256>>>(cb);
    wsplit_kernel<<<(KH * D_EMB) / 256, 256>>>(Ws2, Wf2, bs2, bf2);
    dim3 g2(M_TOTAL / 128, D_EMB / 128);
    embed_hmma_kernel<<<g2, 256, E_SMEM>>>();
    vq_pass1_kernel<<<M_TOTAL / VBM, 256, VQ_SMEM>>>();
    vq_refine_kernel<<<M_TOTAL / 8, 256>>>(cb, out_tok, out_q);
}